// round 3
// baseline (speedup 1.0000x reference)
#include <cuda_runtime.h>
#include <cooperative_groups.h>
#include <math.h>
#include <stdint.h>

namespace cg = cooperative_groups;

#define T_STEPS 32768
#define DIM 256
#define G3 768            // 3*DIM
#define FFN_DIM 1024
#define NC 8              // cluster size (CTAs)
#define SCAN_THREADS 384  // 12 warps, 96 cols x 4 threads/col

// ---------------- scratch (static device allocations; no cudaMalloc allowed) ----
__device__ float g_xg[T_STEPS * G3];
__device__ float g_ys[T_STEPS * DIM];
__device__ float g_t3[T_STEPS * DIM];
__device__ float g_y [T_STEPS * DIM];
__device__ float g_t1[T_STEPS * FFN_DIM];
__device__ float g_t6[T_STEPS * DIM];

// ---------------- packed f32x2 helpers ------------------------------------------
__device__ __forceinline__ unsigned long long pack2(float lo, float hi) {
    unsigned long long r;
    asm("mov.b64 %0, {%1, %2};" : "=l"(r) : "f"(lo), "f"(hi));
    return r;
}
__device__ __forceinline__ unsigned long long dup2(float v) {
    unsigned long long r;
    asm("mov.b64 %0, {%1, %1};" : "=l"(r) : "f"(v));
    return r;
}
__device__ __forceinline__ void fma2(unsigned long long& acc,
                                     unsigned long long a, unsigned long long b) {
    asm("fma.rn.f32x2 %0, %1, %2, %0;" : "+l"(acc) : "l"(a), "l"(b));
}
__device__ __forceinline__ unsigned long long add2(unsigned long long a,
                                                   unsigned long long b) {
    unsigned long long r;
    asm("add.rn.f32x2 %0, %1, %2;" : "=l"(r) : "l"(a), "l"(b));
    return r;
}
__device__ __forceinline__ float hsum2(unsigned long long v) {
    float lo, hi;
    asm("mov.b64 {%0, %1}, %2;" : "=f"(lo), "=f"(hi) : "l"(v));
    return lo + hi;
}

// ---------------- fast transcendentals ------------------------------------------
__device__ __forceinline__ float sigmoid_fast(float x) {
    return __fdividef(1.f, 1.f + __expf(-x));
}
__device__ __forceinline__ float tanh_fast(float x) {
    float e = __expf(2.f * x);
    return 1.f - __fdividef(2.f, e + 1.f);
}

// ---------------- mbarrier helpers ----------------------------------------------
__device__ __forceinline__ uint32_t smem_u32(const void* p) {
    uint32_t a;
    asm("{ .reg .u64 t; cvta.to.shared.u64 t, %1; cvt.u32.u64 %0, t; }"
        : "=r"(a) : "l"(p));
    return a;
}
__device__ __forceinline__ void mbar_init(uint32_t mbar, uint32_t count) {
    asm volatile("mbarrier.init.shared.b64 [%0], %1;" :: "r"(mbar), "r"(count) : "memory");
}
// arrive (release, cluster scope) on the barrier at the same smem offset in CTA `rank`
__device__ __forceinline__ void mbar_arrive_remote(uint32_t local_mbar, uint32_t rank) {
    asm volatile(
        "{\n\t.reg .b32 ra;\n\t"
        "mapa.shared::cluster.u32 ra, %0, %1;\n\t"
        "mbarrier.arrive.release.cluster.shared::cluster.b64 _, [ra];\n\t"
        "}" :: "r"(local_mbar), "r"(rank) : "memory");
}
__device__ __forceinline__ void mbar_wait_cluster(uint32_t mbar, uint32_t parity) {
    asm volatile(
        "{\n\t.reg .pred P;\n\t"
        "WL_%=:\n\t"
        "mbarrier.try_wait.parity.acquire.cluster.shared::cta.b64 P, [%0], %1, 0x989680;\n\t"
        "@P bra.uni WD_%=;\n\t"
        "bra.uni WL_%=;\n\t"
        "WD_%=:\n\t}"
        :: "r"(mbar), "r"(parity) : "memory");
}

// ================================================================================
// GRU scan: 8-CTA cluster, Wh in registers (packed f32x2), mbarrier step sync.
// ================================================================================
__global__ void __cluster_dims__(NC, 1, 1) __launch_bounds__(SCAN_THREADS, 1)
scan_kernel(const float* __restrict__ Wh, const float* __restrict__ bh,
            const float* __restrict__ h0)
{
    cg::cluster_group cluster = cg::this_cluster();
    const unsigned crank = cluster.block_rank();

    __shared__ __align__(16) float h_s[2][DIM];
    __shared__ float hg_s[96];
    __shared__ __align__(8) unsigned long long step_bar;

    const int tid  = threadIdx.x;
    const int lane = tid & 31;
    const int warp = tid >> 5;
    const int col_local = warp * 8 + (lane & 7);   // 0..95
    const int q  = lane >> 3;                      // k-quarter 0..3
    const int qq = 2 * q;                          // bank-conflict rotation
    const int gate = col_local >> 5;               // 0=r,1=z,2=n
    const int m    = col_local & 31;
    const int gcol = gate * DIM + (int)crank * 32 + m;

    const uint32_t bar_addr = smem_u32(&step_bar);
    if (tid == 0) mbar_init(bar_addr, NC * 32);    // 256 arrivals per step

    // ---- 64 weights/thread, packed into 32 f32x2, rotated chunk order ----
    unsigned long long w2[32];
#pragma unroll
    for (int j = 0; j < 16; ++j) {
        const int cidx = (j + qq) & 15;
        const int k = q * 64 + cidx * 4;
        w2[2 * j + 0] = pack2(Wh[(k + 0) * G3 + gcol], Wh[(k + 1) * G3 + gcol]);
        w2[2 * j + 1] = pack2(Wh[(k + 2) * G3 + gcol], Wh[(k + 3) * G3 + gcol]);
    }
    const float bcol = bh[gcol];

    if (tid < DIM) h_s[0][tid] = h0[tid];

    // prefetch xg for t = 0 (gate threads only)
    float xr = 0.f, xz = 0.f, xn = 0.f;
    if (tid < 32) {
        const float* p = g_xg + (int)crank * 32 + tid;
        xr = p[0]; xz = p[DIM]; xn = p[2 * DIM];
    }

    cluster.sync();   // barrier init + h_s[0] visible everywhere

#pragma unroll 1
    for (int t = 0; t < T_STEPS; ++t) {
        // ---- matvec: hg[col] = sum_k h[k] * Wh[k, gcol] (f32x2 packed) ----
        const ulonglong2* hb = (const ulonglong2*)h_s[t & 1] + q * 8;
        unsigned long long a0 = 0ull, a1 = 0ull, a2 = 0ull, a3 = 0ull;
#pragma unroll
        for (int j = 0; j < 16; ++j) {
            const int idx = (j + qq) & 15;       // conflict-free rotation
            const ulonglong2 hv = hb[idx >> 1].x == 0 && false ? hb[0] : ((const ulonglong2*)((const float4*)h_s[t & 1] + q * 16))[idx];
            fma2((j & 1) ? a2 : a0, w2[2 * j + 0], hv.x);
            fma2((j & 1) ? a3 : a1, w2[2 * j + 1], hv.y);
        }
        float acc = hsum2(add2(add2(a0, a1), add2(a2, a3)));
        acc += __shfl_down_sync(0xffffffffu, acc, 16);
        acc += __shfl_down_sync(0xffffffffu, acc, 8);
        if (q == 0) hg_s[col_local] = acc + bcol;
        __syncthreads();

        // ---- gates + state update for our 32 h elements ----
        if (tid < 32) {
            const float hr = hg_s[tid];
            const float hz = hg_s[32 + tid];
            const float hn = hg_s[64 + tid];
            const float r = sigmoid_fast(xr + hr);
            const float z = sigmoid_fast(xz + hz);
            const float nn = tanh_fast(xn + r * hn);
            const float hold = h_s[t & 1][(int)crank * 32 + tid];
            const float hnew = (1.f - z) * nn + z * hold;

            g_ys[t * DIM + (int)crank * 32 + tid] = hnew;

            if (t + 1 < T_STEPS) {
                const float* p = g_xg + (t + 1) * G3 + (int)crank * 32 + tid;
                xr = p[0]; xz = p[DIM]; xn = p[2 * DIM];
            }

            // write h_new into every CTA's next buffer, then release-arrive
            const int nb = (t + 1) & 1;
#pragma unroll
            for (int d = 0; d < NC; ++d) {
                float* dst = cluster.map_shared_rank(&h_s[nb][(int)crank * 32 + tid], d);
                *dst = hnew;
            }
#pragma unroll
            for (int d = 0; d < NC; ++d) mbar_arrive_remote(bar_addr, d);
        }
        mbar_wait_cluster(bar_addr, t & 1);
    }
}

// ================================================================================
// fp32 tiled GEMM with packed f32x2 inner loop.
// BM=BN=128, BK=8, 256 threads, 8x8 micro-tile.
// ================================================================================
__global__ __launch_bounds__(256)
void gemm_kernel(const float* __restrict__ A, const float* __restrict__ B,
                 const float* __restrict__ bias, float* __restrict__ C,
                 int M, int N, int K, int reluA, int reluOut)
{
    constexpr int BM = 128, BN = 128, BK = 8;
    __shared__ __align__(16) float As[BK][BM];
    __shared__ __align__(16) float Bs[BK][BN];

    const int tid = threadIdx.x;
    const int bm = blockIdx.y * BM;
    const int bn = blockIdx.x * BN;
    const int tx = tid & 15;
    const int ty = tid >> 4;

    const int aRow = tid >> 1;
    const int aCol = (tid & 1) * 4;
    const int bRow = tid >> 5;
    const int bCol = (tid & 31) * 4;

    const float* Aptr = A + (size_t)(bm + aRow) * K + aCol;
    const float* Bptr = B + (size_t)bRow * N + bn + bCol;

    unsigned long long acc2[8][4];
#pragma unroll
    for (int i = 0; i < 8; ++i)
#pragma unroll
        for (int j = 0; j < 4; ++j) acc2[i][j] = 0ull;

    for (int k0 = 0; k0 < K; k0 += BK) {
        float4 av = *(const float4*)(Aptr + k0);
        if (reluA) {
            av.x = fmaxf(av.x, 0.f); av.y = fmaxf(av.y, 0.f);
            av.z = fmaxf(av.z, 0.f); av.w = fmaxf(av.w, 0.f);
        }
        As[aCol + 0][aRow] = av.x;
        As[aCol + 1][aRow] = av.y;
        As[aCol + 2][aRow] = av.z;
        As[aCol + 3][aRow] = av.w;
        *(float4*)&Bs[bRow][bCol] = *(const float4*)(Bptr + (size_t)k0 * N);
        __syncthreads();

#pragma unroll
        for (int k = 0; k < BK; ++k) {
            float a[8];
            *(float4*)(a)     = *(const float4*)&As[k][ty * 8];
            *(float4*)(a + 4) = *(const float4*)&As[k][ty * 8 + 4];
            unsigned long long b2[4];
            {
                const ulonglong2 p0 = *(const ulonglong2*)&Bs[k][tx * 8];
                const ulonglong2 p1 = *(const ulonglong2*)&Bs[k][tx * 8 + 4];
                b2[0] = p0.x; b2[1] = p0.y; b2[2] = p1.x; b2[3] = p1.y;
            }
#pragma unroll
            for (int i = 0; i < 8; ++i) {
                const unsigned long long ad = dup2(a[i]);
#pragma unroll
                for (int j = 0; j < 4; ++j) fma2(acc2[i][j], ad, b2[j]);
            }
        }
        __syncthreads();
    }

    float bias_r[8];
#pragma unroll
    for (int j = 0; j < 8; ++j) bias_r[j] = bias ? bias[bn + tx * 8 + j] : 0.f;

#pragma unroll
    for (int i = 0; i < 8; ++i) {
        const int row = bm + ty * 8 + i;
        float* cp = C + (size_t)row * N + bn + tx * 8;
        float o[8];
#pragma unroll
        for (int j = 0; j < 4; ++j) {
            float lo, hi;
            asm("mov.b64 {%0, %1}, %2;" : "=f"(lo), "=f"(hi) : "l"(acc2[i][j]));
            o[2 * j] = lo; o[2 * j + 1] = hi;
        }
#pragma unroll
        for (int j = 0; j < 8; ++j) {
            float v = o[j] + bias_r[j];
            o[j] = reluOut ? fmaxf(v, 0.f) : v;
        }
        *(float4*)cp       = *(float4*)(o);
        *(float4*)(cp + 4) = *(float4*)(o + 4);
    }
}

// ================================================================================
// Fused residual + LayerNorm (rows of 256): out = LN(base + delta)*g + b
// ================================================================================
__global__ __launch_bounds__(256)
void ln_kernel(const float* __restrict__ base, const float* __restrict__ delta,
               const float* __restrict__ g, const float* __restrict__ b,
               float* __restrict__ out)
{
    const int row  = blockIdx.x * 8 + (threadIdx.x >> 5);
    const int lane = threadIdx.x & 31;

    const float4* bp = (const float4*)(base  + (size_t)row * DIM);
    const float4* dp = (const float4*)(delta + (size_t)row * DIM);
    float4 x0 = bp[lane],      d0 = dp[lane];
    float4 x1 = bp[32 + lane], d1 = dp[32 + lane];
    float4 u0, u1;
    u0.x = x0.x + d0.x; u0.y = x0.y + d0.y; u0.z = x0.z + d0.z; u0.w = x0.w + d0.w;
    u1.x = x1.x + d1.x; u1.y = x1.y + d1.y; u1.z = x1.z + d1.z; u1.w = x1.w + d1.w;

    float s  = u0.x + u0.y + u0.z + u0.w + u1.x + u1.y + u1.z + u1.w;
    float ss = u0.x*u0.x + u0.y*u0.y + u0.z*u0.z + u0.w*u0.w
             + u1.x*u1.x + u1.y*u1.y + u1.z*u1.z + u1.w*u1.w;
#pragma unroll
    for (int o = 16; o > 0; o >>= 1) {
        s  += __shfl_xor_sync(0xffffffffu, s, o);
        ss += __shfl_xor_sync(0xffffffffu, ss, o);
    }
    const float mean = s * (1.f / DIM);
    const float var  = ss * (1.f / DIM) - mean * mean;
    const float rstd = rsqrtf(var + 1e-6f);

    const float4 gv0 = ((const float4*)g)[lane];
    const float4 gv1 = ((const float4*)g)[32 + lane];
    const float4 bv0 = ((const float4*)b)[lane];
    const float4 bv1 = ((const float4*)b)[32 + lane];

    float4 o0, o1;
    o0.x = (u0.x - mean) * rstd * gv0.x + bv0.x;
    o0.y = (u0.y - mean) * rstd * gv0.y + bv0.y;
    o0.z = (u0.z - mean) * rstd * gv0.z + bv0.z;
    o0.w = (u0.w - mean) * rstd * gv0.w + bv0.w;
    o1.x = (u1.x - mean) * rstd * gv1.x + bv1.x;
    o1.y = (u1.y - mean) * rstd * gv1.y + bv1.y;
    o1.z = (u1.z - mean) * rstd * gv1.z + bv1.z;
    o1.w = (u1.w - mean) * rstd * gv1.w + bv1.w;

    float4* op = (float4*)(out + (size_t)row * DIM);
    op[lane] = o0;
    op[32 + lane] = o1;
}

// ================================================================================
extern "C" void kernel_launch(void* const* d_in, const int* in_sizes, int n_in,
                              void* d_out, int out_size)
{
    (void)in_sizes; (void)n_in; (void)out_size;
    const float* xs  = (const float*)d_in[0];
    const float* h0  = (const float*)d_in[1];
    const float* Wi  = (const float*)d_in[2];
    const float* Wh  = (const float*)d_in[3];
    const float* bh  = (const float*)d_in[4];
    const float* Wg  = (const float*)d_in[5];
    const float* bg  = (const float*)d_in[6];
    const float* g1  = (const float*)d_in[7];
    const float* be1 = (const float*)d_in[8];
    const float* W1  = (const float*)d_in[9];
    const float* b1  = (const float*)d_in[10];
    const float* W2  = (const float*)d_in[11];
    const float* b2  = (const float*)d_in[12];
    const float* g2  = (const float*)d_in[13];
    const float* be2 = (const float*)d_in[14];
    float* out = (float*)d_out;

    float *xg, *ys, *t3, *y, *t1, *t6;
    cudaGetSymbolAddress((void**)&xg, g_xg);
    cudaGetSymbolAddress((void**)&ys, g_ys);
    cudaGetSymbolAddress((void**)&t3, g_t3);
    cudaGetSymbolAddress((void**)&y,  g_y);
    cudaGetSymbolAddress((void**)&t1, g_t1);
    cudaGetSymbolAddress((void**)&t6, g_t6);

    // 1) xg = xs @ Wi
    gemm_kernel<<<dim3(G3 / 128, T_STEPS / 128), 256>>>(xs, Wi, nullptr, xg,
                                                        T_STEPS, G3, DIM, 0, 0);
    // 2) sequential GRU scan -> ys
    scan_kernel<<<NC, SCAN_THREADS>>>(Wh, bh, h0);
    // 3) t3 = relu(ys) @ Wg + bg
    gemm_kernel<<<dim3(DIM / 128, T_STEPS / 128), 256>>>(ys, Wg, bg, t3,
                                                         T_STEPS, DIM, DIM, 1, 0);
    // 4) y = LN(xs + t3) * g1 + be1
    ln_kernel<<<T_STEPS / 8, 256>>>(xs, t3, g1, be1, y);
    // 5) t1 = relu(y @ W1 + b1)
    gemm_kernel<<<dim3(FFN_DIM / 128, T_STEPS / 128), 256>>>(y, W1, b1, t1,
                                                             T_STEPS, FFN_DIM, DIM, 0, 1);
    // 6) t6 = t1 @ W2 + b2
    gemm_kernel<<<dim3(DIM / 128, T_STEPS / 128), 256>>>(t1, W2, b2, t6,
                                                         T_STEPS, DIM, FFN_DIM, 0, 0);
    // 7) out = LN(y + t6) * g2 + be2
    ln_kernel<<<T_STEPS / 8, 256>>>(y, t6, g2, be2, out);
}

// round 4
// speedup vs baseline: 1.7293x; 1.7293x over previous
#include <cuda_runtime.h>
#include <cooperative_groups.h>
#include <math.h>
#include <stdint.h>

namespace cg = cooperative_groups;

#define T_STEPS 32768
#define DIM 256
#define G3 768            // 3*DIM
#define FFN_DIM 1024
#define NC 8              // cluster size (CTAs)
#define SCAN_THREADS 384  // 12 warps, 96 cols x 4 threads/col

// ---------------- scratch (static device allocations; no cudaMalloc allowed) ----
__device__ float g_xg[T_STEPS * G3];
__device__ float g_ys[T_STEPS * DIM];
__device__ float g_t3[T_STEPS * DIM];
__device__ float g_y [T_STEPS * DIM];
__device__ float g_t1[T_STEPS * FFN_DIM];
__device__ float g_t6[T_STEPS * DIM];

// ---------------- packed f32x2 helpers ------------------------------------------
__device__ __forceinline__ unsigned long long pack2(float lo, float hi) {
    unsigned long long r;
    asm("mov.b64 %0, {%1, %2};" : "=l"(r) : "f"(lo), "f"(hi));
    return r;
}
__device__ __forceinline__ void fma2(unsigned long long& acc,
                                     unsigned long long a, unsigned long long b) {
    asm("fma.rn.f32x2 %0, %1, %2, %0;" : "+l"(acc) : "l"(a), "l"(b));
}
__device__ __forceinline__ unsigned long long add2(unsigned long long a,
                                                   unsigned long long b) {
    unsigned long long r;
    asm("add.rn.f32x2 %0, %1, %2;" : "=l"(r) : "l"(a), "l"(b));
    return r;
}
__device__ __forceinline__ float hsum2(unsigned long long v) {
    float lo, hi;
    asm("mov.b64 {%0, %1}, %2;" : "=f"(lo), "=f"(hi) : "l"(v));
    return lo + hi;
}

// ---------------- fast transcendentals ------------------------------------------
__device__ __forceinline__ float sigmoid_fast(float x) {
    return __fdividef(1.f, 1.f + __expf(-x));
}
__device__ __forceinline__ float tanh_fast(float x) {
    float e = __expf(2.f * x);
    return 1.f - __fdividef(2.f, e + 1.f);
}

// ---------------- mbarrier helpers ----------------------------------------------
__device__ __forceinline__ uint32_t smem_u32(const void* p) {
    uint32_t a;
    asm("{ .reg .u64 t; cvta.to.shared.u64 t, %1; cvt.u32.u64 %0, t; }"
        : "=r"(a) : "l"(p));
    return a;
}
__device__ __forceinline__ void mbar_init(uint32_t mbar, uint32_t count) {
    asm volatile("mbarrier.init.shared.b64 [%0], %1;" :: "r"(mbar), "r"(count) : "memory");
}
// one release-arrive (cluster scope) on the barrier at this smem offset in CTA `rank`
__device__ __forceinline__ void mbar_arrive_remote(uint32_t local_mbar, uint32_t rank) {
    asm volatile(
        "{\n\t.reg .b32 ra;\n\t"
        "mapa.shared::cluster.u32 ra, %0, %1;\n\t"
        "mbarrier.arrive.release.cluster.shared::cluster.b64 _, [ra];\n\t"
        "}" :: "r"(local_mbar), "r"(rank) : "memory");
}
__device__ __forceinline__ void mbar_wait_cluster(uint32_t mbar, uint32_t parity) {
    asm volatile(
        "{\n\t.reg .pred P;\n\t"
        "WL_%=:\n\t"
        "mbarrier.try_wait.parity.acquire.cluster.shared::cta.b64 P, [%0], %1, 0x989680;\n\t"
        "@P bra.uni WD_%=;\n\t"
        "bra.uni WL_%=;\n\t"
        "WD_%=:\n\t}"
        :: "r"(mbar), "r"(parity) : "memory");
}

// ================================================================================
// GRU scan: 8-CTA cluster. Wh in registers (f32x2-packed). Step sync = mbarrier
// with exactly NC(=8) arrivals per barrier per step (lane d arrives on CTA d).
// ================================================================================
__global__ void __cluster_dims__(NC, 1, 1) __launch_bounds__(SCAN_THREADS, 1)
scan_kernel(const float* __restrict__ Wh, const float* __restrict__ bh,
            const float* __restrict__ h0)
{
    cg::cluster_group cluster = cg::this_cluster();
    const unsigned crank = cluster.block_rank();

    __shared__ __align__(16) float h_s[2][DIM];
    __shared__ float hg_s[96];
    __shared__ __align__(8) unsigned long long step_bar;

    const int tid  = threadIdx.x;
    const int lane = tid & 31;
    const int warp = tid >> 5;
    const int col_local = warp * 8 + (lane & 7);   // 0..95
    const int q  = lane >> 3;                      // k-quarter 0..3
    const int qq = 2 * q;                          // bank-conflict rotation
    const int gate = col_local >> 5;               // 0=r,1=z,2=n
    const int m    = col_local & 31;
    const int gcol = gate * DIM + (int)crank * 32 + m;

    const uint32_t bar_addr = smem_u32(&step_bar);
    if (tid == 0) mbar_init(bar_addr, NC);         // 8 arrivals per step

    // ---- 64 weights/thread packed into 32 f32x2, rotated chunk order ----
    unsigned long long w2[32];
#pragma unroll
    for (int j = 0; j < 16; ++j) {
        const int cidx = (j + qq) & 15;
        const int k = q * 64 + cidx * 4;
        w2[2 * j + 0] = pack2(Wh[(k + 0) * G3 + gcol], Wh[(k + 1) * G3 + gcol]);
        w2[2 * j + 1] = pack2(Wh[(k + 2) * G3 + gcol], Wh[(k + 3) * G3 + gcol]);
    }
    const float bcol = bh[gcol];

    if (tid < DIM) h_s[0][tid] = h0[tid];

    // prefetch xg for t = 0 (gate threads only)
    float xr = 0.f, xz = 0.f, xn = 0.f;
    if (tid < 32) {
        const float* p = g_xg + (int)crank * 32 + tid;
        xr = p[0]; xz = p[DIM]; xn = p[2 * DIM];
    }

    cluster.sync();   // barrier init + h_s[0] visible cluster-wide

#pragma unroll 1
    for (int t = 0; t < T_STEPS; ++t) {
        // ---- matvec: hg[col] = sum_k h[k] * Wh[k, gcol]  (f32x2 packed) ----
        const ulonglong2* hb = (const ulonglong2*)(h_s[t & 1]) + q * 16;
        unsigned long long a0 = 0ull, a1 = 0ull, a2 = 0ull, a3 = 0ull;
#pragma unroll
        for (int j = 0; j < 16; ++j) {
            const int idx = (j + qq) & 15;       // conflict-free LDS rotation
            const ulonglong2 hv = hb[idx];
            fma2((j & 1) ? a2 : a0, w2[2 * j + 0], hv.x);
            fma2((j & 1) ? a3 : a1, w2[2 * j + 1], hv.y);
        }
        float acc = hsum2(add2(add2(a0, a1), add2(a2, a3)));
        acc += __shfl_down_sync(0xffffffffu, acc, 16);
        acc += __shfl_down_sync(0xffffffffu, acc, 8);
        if (q == 0) hg_s[col_local] = acc + bcol;
        __syncthreads();

        // ---- gates + state update + cluster broadcast (gate warp only) ----
        if (tid < 32) {
            const float hr = hg_s[tid];
            const float hz = hg_s[32 + tid];
            const float hn = hg_s[64 + tid];
            const float r = sigmoid_fast(xr + hr);
            const float z = sigmoid_fast(xz + hz);
            const float nn = tanh_fast(xn + r * hn);
            const float hold = h_s[t & 1][(int)crank * 32 + tid];
            const float hnew = (1.f - z) * nn + z * hold;

            g_ys[t * DIM + (int)crank * 32 + tid] = hnew;

            if (t + 1 < T_STEPS) {
                const float* p = g_xg + (t + 1) * G3 + (int)crank * 32 + tid;
                xr = p[0]; xz = p[DIM]; xn = p[2 * DIM];
            }

            // write h_new into every CTA's next buffer
            const int nb = (t + 1) & 1;
#pragma unroll
            for (int d = 0; d < NC; ++d) {
                float* dst = cluster.map_shared_rank(&h_s[nb][(int)crank * 32 + tid], d);
                *dst = hnew;
            }
            // order all 32 lanes' remote stores, then ONE arrive per dest CTA
            __syncwarp();
            if (lane < NC) mbar_arrive_remote(bar_addr, (uint32_t)lane);
        }
        mbar_wait_cluster(bar_addr, t & 1);
    }
}

// ================================================================================
// fp32 tiled GEMM (round-1 scalar version, known good):
// C[M,N] = op(A)[M,K] @ B[K,N] (+bias) (+relu). BM=BN=128, BK=8, 256 thr, 8x8.
// ================================================================================
__global__ __launch_bounds__(256)
void gemm_kernel(const float* __restrict__ A, const float* __restrict__ B,
                 const float* __restrict__ bias, float* __restrict__ C,
                 int M, int N, int K, int reluA, int reluOut)
{
    constexpr int BM = 128, BN = 128, BK = 8;
    __shared__ float As[BK][BM];
    __shared__ float Bs[BK][BN];

    const int tid = threadIdx.x;
    const int bm = blockIdx.y * BM;
    const int bn = blockIdx.x * BN;
    const int tx = tid & 15;
    const int ty = tid >> 4;

    const int aRow = tid >> 1;
    const int aCol = (tid & 1) * 4;
    const int bRow = tid >> 5;
    const int bCol = (tid & 31) * 4;

    const float* Aptr = A + (size_t)(bm + aRow) * K + aCol;
    const float* Bptr = B + (size_t)bRow * N + bn + bCol;

    float acc[8][8];
#pragma unroll
    for (int i = 0; i < 8; ++i)
#pragma unroll
        for (int j = 0; j < 8; ++j) acc[i][j] = 0.f;

    for (int k0 = 0; k0 < K; k0 += BK) {
        float4 av = *(const float4*)(Aptr + k0);
        if (reluA) {
            av.x = fmaxf(av.x, 0.f); av.y = fmaxf(av.y, 0.f);
            av.z = fmaxf(av.z, 0.f); av.w = fmaxf(av.w, 0.f);
        }
        As[aCol + 0][aRow] = av.x;
        As[aCol + 1][aRow] = av.y;
        As[aCol + 2][aRow] = av.z;
        As[aCol + 3][aRow] = av.w;
        *(float4*)&Bs[bRow][bCol] = *(const float4*)(Bptr + (size_t)k0 * N);
        __syncthreads();

#pragma unroll
        for (int k = 0; k < BK; ++k) {
            float a[8], b[8];
            *(float4*)(a)     = *(const float4*)&As[k][ty * 8];
            *(float4*)(a + 4) = *(const float4*)&As[k][ty * 8 + 4];
            *(float4*)(b)     = *(const float4*)&Bs[k][tx * 8];
            *(float4*)(b + 4) = *(const float4*)&Bs[k][tx * 8 + 4];
#pragma unroll
            for (int i = 0; i < 8; ++i)
#pragma unroll
                for (int j = 0; j < 8; ++j)
                    acc[i][j] = fmaf(a[i], b[j], acc[i][j]);
        }
        __syncthreads();
    }

    float bias_r[8];
#pragma unroll
    for (int j = 0; j < 8; ++j) bias_r[j] = bias ? bias[bn + tx * 8 + j] : 0.f;

#pragma unroll
    for (int i = 0; i < 8; ++i) {
        const int row = bm + ty * 8 + i;
        float* cp = C + (size_t)row * N + bn + tx * 8;
        float4 o0, o1;
        float v;
        v = acc[i][0] + bias_r[0]; o0.x = reluOut ? fmaxf(v, 0.f) : v;
        v = acc[i][1] + bias_r[1]; o0.y = reluOut ? fmaxf(v, 0.f) : v;
        v = acc[i][2] + bias_r[2]; o0.z = reluOut ? fmaxf(v, 0.f) : v;
        v = acc[i][3] + bias_r[3]; o0.w = reluOut ? fmaxf(v, 0.f) : v;
        v = acc[i][4] + bias_r[4]; o1.x = reluOut ? fmaxf(v, 0.f) : v;
        v = acc[i][5] + bias_r[5]; o1.y = reluOut ? fmaxf(v, 0.f) : v;
        v = acc[i][6] + bias_r[6]; o1.z = reluOut ? fmaxf(v, 0.f) : v;
        v = acc[i][7] + bias_r[7]; o1.w = reluOut ? fmaxf(v, 0.f) : v;
        *(float4*)cp = o0;
        *(float4*)(cp + 4) = o1;
    }
}

// ================================================================================
// Fused residual + LayerNorm (rows of 256): out = LN(base + delta)*g + b
// ================================================================================
__global__ __launch_bounds__(256)
void ln_kernel(const float* __restrict__ base, const float* __restrict__ delta,
               const float* __restrict__ g, const float* __restrict__ b,
               float* __restrict__ out)
{
    const int row  = blockIdx.x * 8 + (threadIdx.x >> 5);
    const int lane = threadIdx.x & 31;

    const float4* bp = (const float4*)(base  + (size_t)row * DIM);
    const float4* dp = (const float4*)(delta + (size_t)row * DIM);
    float4 x0 = bp[lane],      d0 = dp[lane];
    float4 x1 = bp[32 + lane], d1 = dp[32 + lane];
    float4 u0, u1;
    u0.x = x0.x + d0.x; u0.y = x0.y + d0.y; u0.z = x0.z + d0.z; u0.w = x0.w + d0.w;
    u1.x = x1.x + d1.x; u1.y = x1.y + d1.y; u1.z = x1.z + d1.z; u1.w = x1.w + d1.w;

    float s  = u0.x + u0.y + u0.z + u0.w + u1.x + u1.y + u1.z + u1.w;
    float ss = u0.x*u0.x + u0.y*u0.y + u0.z*u0.z + u0.w*u0.w
             + u1.x*u1.x + u1.y*u1.y + u1.z*u1.z + u1.w*u1.w;
#pragma unroll
    for (int o = 16; o > 0; o >>= 1) {
        s  += __shfl_xor_sync(0xffffffffu, s, o);
        ss += __shfl_xor_sync(0xffffffffu, ss, o);
    }
    const float mean = s * (1.f / DIM);
    const float var  = ss * (1.f / DIM) - mean * mean;
    const float rstd = rsqrtf(var + 1e-6f);

    const float4 gv0 = ((const float4*)g)[lane];
    const float4 gv1 = ((const float4*)g)[32 + lane];
    const float4 bv0 = ((const float4*)b)[lane];
    const float4 bv1 = ((const float4*)b)[32 + lane];

    float4 o0, o1;
    o0.x = (u0.x - mean) * rstd * gv0.x + bv0.x;
    o0.y = (u0.y - mean) * rstd * gv0.y + bv0.y;
    o0.z = (u0.z - mean) * rstd * gv0.z + bv0.z;
    o0.w = (u0.w - mean) * rstd * gv0.w + bv0.w;
    o1.x = (u1.x - mean) * rstd * gv1.x + bv1.x;
    o1.y = (u1.y - mean) * rstd * gv1.y + bv1.y;
    o1.z = (u1.z - mean) * rstd * gv1.z + bv1.z;
    o1.w = (u1.w - mean) * rstd * gv1.w + bv1.w;

    float4* op = (float4*)(out + (size_t)row * DIM);
    op[lane] = o0;
    op[32 + lane] = o1;
}

// ================================================================================
extern "C" void kernel_launch(void* const* d_in, const int* in_sizes, int n_in,
                              void* d_out, int out_size)
{
    (void)in_sizes; (void)n_in; (void)out_size;
    const float* xs  = (const float*)d_in[0];
    const float* h0  = (const float*)d_in[1];
    const float* Wi  = (const float*)d_in[2];
    const float* Wh  = (const float*)d_in[3];
    const float* bh  = (const float*)d_in[4];
    const float* Wg  = (const float*)d_in[5];
    const float* bg  = (const float*)d_in[6];
    const float* g1  = (const float*)d_in[7];
    const float* be1 = (const float*)d_in[8];
    const float* W1  = (const float*)d_in[9];
    const float* b1  = (const float*)d_in[10];
    const float* W2  = (const float*)d_in[11];
    const float* b2  = (const float*)d_in[12];
    const float* g2  = (const float*)d_in[13];
    const float* be2 = (const float*)d_in[14];
    float* out = (float*)d_out;

    float *xg, *ys, *t3, *y, *t1, *t6;
    cudaGetSymbolAddress((void**)&xg, g_xg);
    cudaGetSymbolAddress((void**)&ys, g_ys);
    cudaGetSymbolAddress((void**)&t3, g_t3);
    cudaGetSymbolAddress((void**)&y,  g_y);
    cudaGetSymbolAddress((void**)&t1, g_t1);
    cudaGetSymbolAddress((void**)&t6, g_t6);

    // 1) xg = xs @ Wi
    gemm_kernel<<<dim3(G3 / 128, T_STEPS / 128), 256>>>(xs, Wi, nullptr, xg,
                                                        T_STEPS, G3, DIM, 0, 0);
    // 2) sequential GRU scan -> ys
    scan_kernel<<<NC, SCAN_THREADS>>>(Wh, bh, h0);
    // 3) t3 = relu(ys) @ Wg + bg
    gemm_kernel<<<dim3(DIM / 128, T_STEPS / 128), 256>>>(ys, Wg, bg, t3,
                                                         T_STEPS, DIM, DIM, 1, 0);
    // 4) y = LN(xs + t3) * g1 + be1
    ln_kernel<<<T_STEPS / 8, 256>>>(xs, t3, g1, be1, y);
    // 5) t1 = relu(y @ W1 + b1)
    gemm_kernel<<<dim3(FFN_DIM / 128, T_STEPS / 128), 256>>>(y, W1, b1, t1,
                                                             T_STEPS, FFN_DIM, DIM, 0, 1);
    // 6) t6 = t1 @ W2 + b2
    gemm_kernel<<<dim3(DIM / 128, T_STEPS / 128), 256>>>(t1, W2, b2, t6,
                                                         T_STEPS, DIM, FFN_DIM, 0, 0);
    // 7) out = LN(y + t6) * g2 + be2
    ln_kernel<<<T_STEPS / 8, 256>>>(y, t6, g2, be2, out);
}

// round 5
// speedup vs baseline: 2.4091x; 1.3931x over previous
#include <cuda_runtime.h>
#include <cooperative_groups.h>
#include <math.h>
#include <stdint.h>

namespace cg = cooperative_groups;

#define T_STEPS 32768
#define DIM 256
#define G3 768            // 3*DIM
#define FFN_DIM 1024
#define NC 8              // cluster size (CTAs)
#define SCAN_THREADS 384  // 12 warps, 96 cols x 4 threads/col

// ---------------- scratch (static device allocations; no cudaMalloc allowed) ----
__device__ float g_xg[T_STEPS * G3];
__device__ float g_ys[T_STEPS * DIM];
__device__ float g_t3[T_STEPS * DIM];
__device__ float g_y [T_STEPS * DIM];
__device__ float g_t1[T_STEPS * FFN_DIM];
__device__ float g_t6[T_STEPS * DIM];

// ---------------- packed f32x2 helpers ------------------------------------------
__device__ __forceinline__ unsigned long long pack2(float lo, float hi) {
    unsigned long long r;
    asm("mov.b64 %0, {%1, %2};" : "=l"(r) : "f"(lo), "f"(hi));
    return r;
}
__device__ __forceinline__ void fma2(unsigned long long& acc,
                                     unsigned long long a, unsigned long long b) {
    asm("fma.rn.f32x2 %0, %1, %2, %0;" : "+l"(acc) : "l"(a), "l"(b));
}
__device__ __forceinline__ unsigned long long add2(unsigned long long a,
                                                   unsigned long long b) {
    unsigned long long r;
    asm("add.rn.f32x2 %0, %1, %2;" : "=l"(r) : "l"(a), "l"(b));
    return r;
}
__device__ __forceinline__ float hsum2(unsigned long long v) {
    float lo, hi;
    asm("mov.b64 {%0, %1}, %2;" : "=f"(lo), "=f"(hi) : "l"(v));
    return lo + hi;
}

// ---------------- fast transcendentals ------------------------------------------
__device__ __forceinline__ float sigmoid_fast(float x) {
    return __fdividef(1.f, 1.f + __expf(-x));
}
__device__ __forceinline__ float tanh_fast(float x) {
    float e = __expf(2.f * x);
    return 1.f - __fdividef(2.f, e + 1.f);
}

// ---------------- split cluster barrier ------------------------------------------
__device__ __forceinline__ void cluster_arrive_rel() {
    asm volatile("barrier.cluster.arrive.aligned;" ::: "memory");
}
__device__ __forceinline__ void cluster_wait_acq() {
    asm volatile("barrier.cluster.wait.aligned;" ::: "memory");
}

// ================================================================================
// GRU scan: 8-CTA cluster, Wh in registers (f32x2), split cluster barrier.
// CTA c owns h[c*32..c*32+32) and Wh columns {g*256 + c*32 + m}.
// ================================================================================
__global__ void __cluster_dims__(NC, 1, 1) __launch_bounds__(SCAN_THREADS, 1)
scan_kernel(const float* __restrict__ Wh, const float* __restrict__ bh,
            const float* __restrict__ h0)
{
    cg::cluster_group cluster = cg::this_cluster();
    const unsigned crank = cluster.block_rank();

    __shared__ __align__(16) float h_s[2][DIM];
    __shared__ float hg_s[96];

    const int tid  = threadIdx.x;
    const int lane = tid & 31;
    const int warp = tid >> 5;
    const int col_local = warp * 8 + (lane & 7);   // 0..95
    const int q  = lane >> 3;                      // k-quarter 0..3
    const int qq = 2 * q;                          // bank-conflict rotation
    const int gate = col_local >> 5;               // 0=r,1=z,2=n
    const int m    = col_local & 31;
    const int gcol = gate * DIM + (int)crank * 32 + m;

    // ---- 64 weights/thread packed into 32 f32x2, rotated chunk order ----
    unsigned long long w2[32];
#pragma unroll
    for (int j = 0; j < 16; ++j) {
        const int cidx = (j + qq) & 15;
        const int k = q * 64 + cidx * 4;
        w2[2 * j + 0] = pack2(Wh[(k + 0) * G3 + gcol], Wh[(k + 1) * G3 + gcol]);
        w2[2 * j + 1] = pack2(Wh[(k + 2) * G3 + gcol], Wh[(k + 3) * G3 + gcol]);
    }
    const float bcol = bh[gcol];

    if (tid < DIM) h_s[0][tid] = h0[tid];

    // gate-warp-only state: xg prefetch + precomputed remote store pointers
    float xr = 0.f, xz = 0.f, xn = 0.f;
    float* rdst[NC];   // -> peer d's h_s[0][crank*32 + tid]; buffer 1 = +DIM floats
    if (tid < 32) {
        const float* p = g_xg + (int)crank * 32 + tid;
        xr = p[0]; xz = p[DIM]; xn = p[2 * DIM];
#pragma unroll
        for (int d = 0; d < NC; ++d)
            rdst[d] = cluster.map_shared_rank(&h_s[0][(int)crank * 32 + tid], d);
    }

    __syncthreads();       // h_s[0] written locally
    cluster_arrive_rel();  // release h_s[0]; matched by wait at loop top

#pragma unroll 1
    for (int t = 0; t < T_STEPS; ++t) {
        cluster_wait_acq();   // h_s[t&1] complete cluster-wide

        // ---- matvec: hg[col] = sum_k h[k] * Wh[k, gcol]  (f32x2 packed) ----
        const ulonglong2* hb = (const ulonglong2*)(h_s[t & 1]) + q * 16;
        unsigned long long a0 = 0ull, a1 = 0ull, a2 = 0ull, a3 = 0ull;
#pragma unroll
        for (int j = 0; j < 16; ++j) {
            const int idx = (j + qq) & 15;       // conflict-free LDS rotation
            const ulonglong2 hv = hb[idx];
            fma2((j & 1) ? a2 : a0, w2[2 * j + 0], hv.x);
            fma2((j & 1) ? a3 : a1, w2[2 * j + 1], hv.y);
        }
        float acc = hsum2(add2(add2(a0, a1), add2(a2, a3)));
        acc += __shfl_down_sync(0xffffffffu, acc, 16);
        acc += __shfl_down_sync(0xffffffffu, acc, 8);
        if (q == 0) hg_s[col_local] = acc + bcol;
        __syncthreads();

        // ---- gates + remote broadcast (gate warp only), then release-arrive ----
        float hnew = 0.f;
        if (tid < 32) {
            const float hr = hg_s[tid];
            const float hz = hg_s[32 + tid];
            const float hn = hg_s[64 + tid];
            const float r = sigmoid_fast(xr + hr);
            const float z = sigmoid_fast(xz + hz);
            const float nn = tanh_fast(xn + r * hn);
            const float hold = h_s[t & 1][(int)crank * 32 + tid];
            hnew = (1.f - z) * nn + z * hold;

            const int boff = ((t + 1) & 1) << 8;   // +DIM floats for buffer 1
#pragma unroll
            for (int d = 0; d < NC; ++d)
                *(rdst[d] + boff) = hnew;
        }
        cluster_arrive_rel();   // gate warp's arrive releases its stores

        // off the critical path: record output + prefetch next xg
        if (tid < 32) {
            g_ys[t * DIM + (int)crank * 32 + tid] = hnew;
            if (t + 1 < T_STEPS) {
                const float* p = g_xg + (t + 1) * G3 + (int)crank * 32 + tid;
                xr = p[0]; xz = p[DIM]; xn = p[2 * DIM];
            }
        }
    }
    cluster_wait_acq();   // balance final arrive before exit
}

// ================================================================================
// fp32 tiled GEMM (round-1 scalar version, known good):
// C[M,N] = op(A)[M,K] @ B[K,N] (+bias) (+relu). BM=BN=128, BK=8, 256 thr, 8x8.
// ================================================================================
__global__ __launch_bounds__(256)
void gemm_kernel(const float* __restrict__ A, const float* __restrict__ B,
                 const float* __restrict__ bias, float* __restrict__ C,
                 int M, int N, int K, int reluA, int reluOut)
{
    constexpr int BM = 128, BN = 128, BK = 8;
    __shared__ float As[BK][BM];
    __shared__ float Bs[BK][BN];

    const int tid = threadIdx.x;
    const int bm = blockIdx.y * BM;
    const int bn = blockIdx.x * BN;
    const int tx = tid & 15;
    const int ty = tid >> 4;

    const int aRow = tid >> 1;
    const int aCol = (tid & 1) * 4;
    const int bRow = tid >> 5;
    const int bCol = (tid & 31) * 4;

    const float* Aptr = A + (size_t)(bm + aRow) * K + aCol;
    const float* Bptr = B + (size_t)bRow * N + bn + bCol;

    float acc[8][8];
#pragma unroll
    for (int i = 0; i < 8; ++i)
#pragma unroll
        for (int j = 0; j < 8; ++j) acc[i][j] = 0.f;

    for (int k0 = 0; k0 < K; k0 += BK) {
        float4 av = *(const float4*)(Aptr + k0);
        if (reluA) {
            av.x = fmaxf(av.x, 0.f); av.y = fmaxf(av.y, 0.f);
            av.z = fmaxf(av.z, 0.f); av.w = fmaxf(av.w, 0.f);
        }
        As[aCol + 0][aRow] = av.x;
        As[aCol + 1][aRow] = av.y;
        As[aCol + 2][aRow] = av.z;
        As[aCol + 3][aRow] = av.w;
        *(float4*)&Bs[bRow][bCol] = *(const float4*)(Bptr + (size_t)k0 * N);
        __syncthreads();

#pragma unroll
        for (int k = 0; k < BK; ++k) {
            float a[8], b[8];
            *(float4*)(a)     = *(const float4*)&As[k][ty * 8];
            *(float4*)(a + 4) = *(const float4*)&As[k][ty * 8 + 4];
            *(float4*)(b)     = *(const float4*)&Bs[k][tx * 8];
            *(float4*)(b + 4) = *(const float4*)&Bs[k][tx * 8 + 4];
#pragma unroll
            for (int i = 0; i < 8; ++i)
#pragma unroll
                for (int j = 0; j < 8; ++j)
                    acc[i][j] = fmaf(a[i], b[j], acc[i][j]);
        }
        __syncthreads();
    }

    float bias_r[8];
#pragma unroll
    for (int j = 0; j < 8; ++j) bias_r[j] = bias ? bias[bn + tx * 8 + j] : 0.f;

#pragma unroll
    for (int i = 0; i < 8; ++i) {
        const int row = bm + ty * 8 + i;
        float* cp = C + (size_t)row * N + bn + tx * 8;
        float4 o0, o1;
        float v;
        v = acc[i][0] + bias_r[0]; o0.x = reluOut ? fmaxf(v, 0.f) : v;
        v = acc[i][1] + bias_r[1]; o0.y = reluOut ? fmaxf(v, 0.f) : v;
        v = acc[i][2] + bias_r[2]; o0.z = reluOut ? fmaxf(v, 0.f) : v;
        v = acc[i][3] + bias_r[3]; o0.w = reluOut ? fmaxf(v, 0.f) : v;
        v = acc[i][4] + bias_r[4]; o1.x = reluOut ? fmaxf(v, 0.f) : v;
        v = acc[i][5] + bias_r[5]; o1.y = reluOut ? fmaxf(v, 0.f) : v;
        v = acc[i][6] + bias_r[6]; o1.z = reluOut ? fmaxf(v, 0.f) : v;
        v = acc[i][7] + bias_r[7]; o1.w = reluOut ? fmaxf(v, 0.f) : v;
        *(float4*)cp = o0;
        *(float4*)(cp + 4) = o1;
    }
}

// ================================================================================
// Fused residual + LayerNorm (rows of 256): out = LN(base + delta)*g + b
// ================================================================================
__global__ __launch_bounds__(256)
void ln_kernel(const float* __restrict__ base, const float* __restrict__ delta,
               const float* __restrict__ g, const float* __restrict__ b,
               float* __restrict__ out)
{
    const int row  = blockIdx.x * 8 + (threadIdx.x >> 5);
    const int lane = threadIdx.x & 31;

    const float4* bp = (const float4*)(base  + (size_t)row * DIM);
    const float4* dp = (const float4*)(delta + (size_t)row * DIM);
    float4 x0 = bp[lane],      d0 = dp[lane];
    float4 x1 = bp[32 + lane], d1 = dp[32 + lane];
    float4 u0, u1;
    u0.x = x0.x + d0.x; u0.y = x0.y + d0.y; u0.z = x0.z + d0.z; u0.w = x0.w + d0.w;
    u1.x = x1.x + d1.x; u1.y = x1.y + d1.y; u1.z = x1.z + d1.z; u1.w = x1.w + d1.w;

    float s  = u0.x + u0.y + u0.z + u0.w + u1.x + u1.y + u1.z + u1.w;
    float ss = u0.x*u0.x + u0.y*u0.y + u0.z*u0.z + u0.w*u0.w
             + u1.x*u1.x + u1.y*u1.y + u1.z*u1.z + u1.w*u1.w;
#pragma unroll
    for (int o = 16; o > 0; o >>= 1) {
        s  += __shfl_xor_sync(0xffffffffu, s, o);
        ss += __shfl_xor_sync(0xffffffffu, ss, o);
    }
    const float mean = s * (1.f / DIM);
    const float var  = ss * (1.f / DIM) - mean * mean;
    const float rstd = rsqrtf(var + 1e-6f);

    const float4 gv0 = ((const float4*)g)[lane];
    const float4 gv1 = ((const float4*)g)[32 + lane];
    const float4 bv0 = ((const float4*)b)[lane];
    const float4 bv1 = ((const float4*)b)[32 + lane];

    float4 o0, o1;
    o0.x = (u0.x - mean) * rstd * gv0.x + bv0.x;
    o0.y = (u0.y - mean) * rstd * gv0.y + bv0.y;
    o0.z = (u0.z - mean) * rstd * gv0.z + bv0.z;
    o0.w = (u0.w - mean) * rstd * gv0.w + bv0.w;
    o1.x = (u1.x - mean) * rstd * gv1.x + bv1.x;
    o1.y = (u1.y - mean) * rstd * gv1.y + bv1.y;
    o1.z = (u1.z - mean) * rstd * gv1.z + bv1.z;
    o1.w = (u1.w - mean) * rstd * gv1.w + bv1.w;

    float4* op = (float4*)(out + (size_t)row * DIM);
    op[lane] = o0;
    op[32 + lane] = o1;
}

// ================================================================================
extern "C" void kernel_launch(void* const* d_in, const int* in_sizes, int n_in,
                              void* d_out, int out_size)
{
    (void)in_sizes; (void)n_in; (void)out_size;
    const float* xs  = (const float*)d_in[0];
    const float* h0  = (const float*)d_in[1];
    const float* Wi  = (const float*)d_in[2];
    const float* Wh  = (const float*)d_in[3];
    const float* bh  = (const float*)d_in[4];
    const float* Wg  = (const float*)d_in[5];
    const float* bg  = (const float*)d_in[6];
    const float* g1  = (const float*)d_in[7];
    const float* be1 = (const float*)d_in[8];
    const float* W1  = (const float*)d_in[9];
    const float* b1  = (const float*)d_in[10];
    const float* W2  = (const float*)d_in[11];
    const float* b2  = (const float*)d_in[12];
    const float* g2  = (const float*)d_in[13];
    const float* be2 = (const float*)d_in[14];
    float* out = (float*)d_out;

    float *xg, *ys, *t3, *y, *t1, *t6;
    cudaGetSymbolAddress((void**)&xg, g_xg);
    cudaGetSymbolAddress((void**)&ys, g_ys);
    cudaGetSymbolAddress((void**)&t3, g_t3);
    cudaGetSymbolAddress((void**)&y,  g_y);
    cudaGetSymbolAddress((void**)&t1, g_t1);
    cudaGetSymbolAddress((void**)&t6, g_t6);

    // 1) xg = xs @ Wi
    gemm_kernel<<<dim3(G3 / 128, T_STEPS / 128), 256>>>(xs, Wi, nullptr, xg,
                                                        T_STEPS, G3, DIM, 0, 0);
    // 2) sequential GRU scan -> ys
    scan_kernel<<<NC, SCAN_THREADS>>>(Wh, bh, h0);
    // 3) t3 = relu(ys) @ Wg + bg
    gemm_kernel<<<dim3(DIM / 128, T_STEPS / 128), 256>>>(ys, Wg, bg, t3,
                                                         T_STEPS, DIM, DIM, 1, 0);
    // 4) y = LN(xs + t3) * g1 + be1
    ln_kernel<<<T_STEPS / 8, 256>>>(xs, t3, g1, be1, y);
    // 5) t1 = relu(y @ W1 + b1)
    gemm_kernel<<<dim3(FFN_DIM / 128, T_STEPS / 128), 256>>>(y, W1, b1, t1,
                                                             T_STEPS, FFN_DIM, DIM, 0, 1);
    // 6) t6 = t1 @ W2 + b2
    gemm_kernel<<<dim3(DIM / 128, T_STEPS / 128), 256>>>(t1, W2, b2, t6,
                                                         T_STEPS, DIM, FFN_DIM, 0, 0);
    // 7) out = LN(y + t6) * g2 + be2
    ln_kernel<<<T_STEPS / 8, 256>>>(y, t6, g2, be2, out);
}

// round 6
// speedup vs baseline: 3.2435x; 1.3463x over previous
#include <cuda_runtime.h>
#include <cooperative_groups.h>
#include <math.h>
#include <stdint.h>

namespace cg = cooperative_groups;

#define T_STEPS 32768
#define DIM 256
#define G3 768            // 3*DIM
#define FFN_DIM 1024
#define NC 8              // cluster size (CTAs)
#define SCAN_THREADS 384  // 12 warps, 96 cols x 4 threads/col
#define TX_BYTES 1024     // per-step bytes into each CTA: 8 CTAs * 16 lanes * 8B

// ---------------- scratch (static device allocations; no cudaMalloc allowed) ----
__device__ float g_xg[T_STEPS * G3];
__device__ float g_ys[T_STEPS * DIM];
__device__ float g_t3[T_STEPS * DIM];
__device__ float g_y [T_STEPS * DIM];
__device__ float g_t1[T_STEPS * FFN_DIM];
__device__ float g_t6[T_STEPS * DIM];

// ---------------- packed f32x2 helpers ------------------------------------------
__device__ __forceinline__ unsigned long long pack2(float lo, float hi) {
    unsigned long long r;
    asm("mov.b64 %0, {%1, %2};" : "=l"(r) : "f"(lo), "f"(hi));
    return r;
}
__device__ __forceinline__ void fma2(unsigned long long& acc,
                                     unsigned long long a, unsigned long long b) {
    asm("fma.rn.f32x2 %0, %1, %2, %0;" : "+l"(acc) : "l"(a), "l"(b));
}
__device__ __forceinline__ unsigned long long add2(unsigned long long a,
                                                   unsigned long long b) {
    unsigned long long r;
    asm("add.rn.f32x2 %0, %1, %2;" : "=l"(r) : "l"(a), "l"(b));
    return r;
}
__device__ __forceinline__ float hsum2(unsigned long long v) {
    float lo, hi;
    asm("mov.b64 {%0, %1}, %2;" : "=f"(lo), "=f"(hi) : "l"(v));
    return lo + hi;
}

// ---------------- fast transcendentals ------------------------------------------
__device__ __forceinline__ float sigmoid_fast(float x) {
    return __fdividef(1.f, 1.f + __expf(-x));
}
__device__ __forceinline__ float tanh_fast(float x) {
    float e = __expf(2.f * x);
    return 1.f - __fdividef(2.f, e + 1.f);
}

// ---------------- smem / cluster primitives --------------------------------------
__device__ __forceinline__ uint32_t smem_u32(const void* p) {
    uint32_t a;
    asm("{ .reg .u64 t; cvta.to.shared.u64 t, %1; cvt.u32.u64 %0, t; }"
        : "=r"(a) : "l"(p));
    return a;
}
__device__ __forceinline__ uint32_t mapa_u32(uint32_t laddr, uint32_t rank) {
    uint32_t r;
    asm("mapa.shared::cluster.u32 %0, %1, %2;" : "=r"(r) : "r"(laddr), "r"(rank));
    return r;
}
__device__ __forceinline__ void mbar_init(uint32_t mbar, uint32_t count) {
    asm volatile("mbarrier.init.shared.b64 [%0], %1;" :: "r"(mbar), "r"(count) : "memory");
}
__device__ __forceinline__ void mbar_arrive_expect_tx(uint32_t mbar, uint32_t bytes) {
    asm volatile("mbarrier.arrive.expect_tx.shared.b64 _, [%0], %1;"
                 :: "r"(mbar), "r"(bytes) : "memory");
}
__device__ __forceinline__ void mbar_wait_parity_acq(uint32_t mbar, uint32_t parity) {
    asm volatile(
        "{\n\t.reg .pred P;\n\t"
        "WL_%=:\n\t"
        "mbarrier.try_wait.parity.acquire.cluster.shared::cta.b64 P, [%0], %1, 0x989680;\n\t"
        "@P bra.uni WD_%=;\n\t"
        "bra.uni WL_%=;\n\t"
        "WD_%=:\n\t}"
        :: "r"(mbar), "r"(parity) : "memory");
}
// async 8-byte store into a peer CTA's smem; signals the peer-local mbarrier's tx count
__device__ __forceinline__ void st_async_b64(uint32_t raddr, unsigned long long v,
                                             uint32_t rmbar) {
    asm volatile(
        "st.async.shared::cluster.mbarrier::complete_tx::bytes.b64 [%0], %1, [%2];"
        :: "r"(raddr), "l"(v), "r"(rmbar) : "memory");
}
__device__ __forceinline__ void cluster_arrive_rel() {
    asm volatile("barrier.cluster.arrive.aligned;" ::: "memory");
}
__device__ __forceinline__ void cluster_wait_acq() {
    asm volatile("barrier.cluster.wait.aligned;" ::: "memory");
}

// ================================================================================
// GRU scan: 8-CTA cluster. Wh in registers (f32x2). Step sync = st.async into
// peers' double-buffered h + local transaction-counting mbarrier (no cluster bar).
// ================================================================================
__global__ void __cluster_dims__(NC, 1, 1) __launch_bounds__(SCAN_THREADS, 1)
scan_kernel(const float* __restrict__ Wh, const float* __restrict__ bh,
            const float* __restrict__ h0)
{
    cg::cluster_group cluster = cg::this_cluster();
    const unsigned crank = cluster.block_rank();

    __shared__ __align__(16) float h_s[2][DIM];
    __shared__ float hg_s[96];
    __shared__ __align__(8) unsigned long long mbar[2];

    const int tid  = threadIdx.x;
    const int lane = tid & 31;
    const int warp = tid >> 5;
    const int col_local = warp * 8 + (lane & 7);   // 0..95
    const int q  = lane >> 3;                      // k-quarter 0..3
    const int qq = 2 * q;                          // bank-conflict rotation
    const int gate = col_local >> 5;               // 0=r,1=z,2=n
    const int m    = col_local & 31;
    const int gcol = gate * DIM + (int)crank * 32 + m;

    const uint32_t mbar0 = smem_u32(&mbar[0]);
    if (tid == 0) { mbar_init(mbar0, 1); mbar_init(mbar0 + 8, 1); }

    // ---- 64 weights/thread packed into 32 f32x2, rotated chunk order ----
    unsigned long long w2[32];
#pragma unroll
    for (int j = 0; j < 16; ++j) {
        const int cidx = (j + qq) & 15;
        const int k = q * 64 + cidx * 4;
        w2[2 * j + 0] = pack2(Wh[(k + 0) * G3 + gcol], Wh[(k + 1) * G3 + gcol]);
        w2[2 * j + 1] = pack2(Wh[(k + 2) * G3 + gcol], Wh[(k + 3) * G3 + gcol]);
    }
    const float bcol = bh[gcol];

    if (tid < DIM) h_s[0][tid] = h0[tid];

    // gate-warp-only: xg prefetch + remote addresses (even lanes store pairs)
    float xr = 0.f, xz = 0.f, xn = 0.f;
    uint32_t rdata[NC], rmbar[NC];
    if (tid < 32) {
        const float* p = g_xg + (int)crank * 32 + tid;
        xr = p[0]; xz = p[DIM]; xn = p[2 * DIM];
        const uint32_t ldata = smem_u32(&h_s[0][(int)crank * 32 + lane]);
#pragma unroll
        for (int d = 0; d < NC; ++d) {
            rdata[d] = mapa_u32(ldata, (uint32_t)d);
            rmbar[d] = mapa_u32(mbar0, (uint32_t)d);
        }
    }

    __syncthreads();
    cluster.sync();   // mbarrier inits + h_s[0] visible cluster-wide

#pragma unroll 1
    for (int t = 0; t < T_STEPS; ++t) {
        const int b = t & 1;
        if (t > 0)
            mbar_wait_parity_acq(mbar0 + (uint32_t)(b * 8), (uint32_t)(((t - 1) >> 1) & 1));
        if (tid == 0 && t + 1 < T_STEPS)
            mbar_arrive_expect_tx(mbar0 + (uint32_t)(((t + 1) & 1) * 8), TX_BYTES);

        // ---- matvec: hg[col] = sum_k h[k] * Wh[k, gcol]  (f32x2 packed) ----
        const ulonglong2* hb = (const ulonglong2*)(h_s[b]) + q * 16;
        unsigned long long a0 = 0ull, a1 = 0ull, a2 = 0ull, a3 = 0ull;
#pragma unroll
        for (int j = 0; j < 16; ++j) {
            const int idx = (j + qq) & 15;       // conflict-free LDS rotation
            const ulonglong2 hv = hb[idx];
            fma2((j & 1) ? a2 : a0, w2[2 * j + 0], hv.x);
            fma2((j & 1) ? a3 : a1, w2[2 * j + 1], hv.y);
        }
        float acc = hsum2(add2(add2(a0, a1), add2(a2, a3)));
        acc += __shfl_down_sync(0xffffffffu, acc, 16);
        acc += __shfl_down_sync(0xffffffffu, acc, 8);
        if (q == 0) hg_s[col_local] = acc + bcol;
        __syncthreads();

        // ---- gates + async broadcast (gate warp only) ----
        if (tid < 32) {
            const float hr = hg_s[tid];
            const float hz = hg_s[32 + tid];
            const float hn = hg_s[64 + tid];
            const float r = sigmoid_fast(xr + hr);
            const float z = sigmoid_fast(xz + hz);
            const float nn = tanh_fast(xn + r * hn);
            const float hold = h_s[b][(int)crank * 32 + tid];
            const float hnew = (1.f - z) * nn + z * hold;

            // pack (even, odd) neighbor pair; even lanes push 8B to all peers
            const float hhi = __shfl_down_sync(0xffffffffu, hnew, 1);
            if (t + 1 < T_STEPS && !(lane & 1)) {
                const unsigned long long pv = pack2(hnew, hhi);
                const uint32_t boff = (uint32_t)(((t + 1) & 1) * (DIM * 4));
                const uint32_t moff = (uint32_t)(((t + 1) & 1) * 8);
#pragma unroll
                for (int d = 0; d < NC; ++d)
                    st_async_b64(rdata[d] + boff, pv, rmbar[d] + moff);
            }

            // off the critical path: record output + prefetch next xg
            g_ys[t * DIM + (int)crank * 32 + tid] = hnew;
            if (t + 1 < T_STEPS) {
                const float* p = g_xg + (t + 1) * G3 + (int)crank * 32 + tid;
                xr = p[0]; xz = p[DIM]; xn = p[2 * DIM];
            }
        }
        __syncthreads();   // keep non-gate warps from racing ahead into next matvec
    }

    // keep cluster smem alive until all peers are done (drains in-flight traffic)
    cluster_arrive_rel();
    cluster_wait_acq();
}

// ================================================================================
// fp32 tiled GEMM (known good): C = op(A)@B (+bias)(+relu). 128x128x8, 8x8/thread.
// ================================================================================
__global__ __launch_bounds__(256)
void gemm_kernel(const float* __restrict__ A, const float* __restrict__ B,
                 const float* __restrict__ bias, float* __restrict__ C,
                 int M, int N, int K, int reluA, int reluOut)
{
    constexpr int BM = 128, BN = 128, BK = 8;
    __shared__ float As[BK][BM];
    __shared__ float Bs[BK][BN];

    const int tid = threadIdx.x;
    const int bm = blockIdx.y * BM;
    const int bn = blockIdx.x * BN;
    const int tx = tid & 15;
    const int ty = tid >> 4;

    const int aRow = tid >> 1;
    const int aCol = (tid & 1) * 4;
    const int bRow = tid >> 5;
    const int bCol = (tid & 31) * 4;

    const float* Aptr = A + (size_t)(bm + aRow) * K + aCol;
    const float* Bptr = B + (size_t)bRow * N + bn + bCol;

    float acc[8][8];
#pragma unroll
    for (int i = 0; i < 8; ++i)
#pragma unroll
        for (int j = 0; j < 8; ++j) acc[i][j] = 0.f;

    for (int k0 = 0; k0 < K; k0 += BK) {
        float4 av = *(const float4*)(Aptr + k0);
        if (reluA) {
            av.x = fmaxf(av.x, 0.f); av.y = fmaxf(av.y, 0.f);
            av.z = fmaxf(av.z, 0.f); av.w = fmaxf(av.w, 0.f);
        }
        As[aCol + 0][aRow] = av.x;
        As[aCol + 1][aRow] = av.y;
        As[aCol + 2][aRow] = av.z;
        As[aCol + 3][aRow] = av.w;
        *(float4*)&Bs[bRow][bCol] = *(const float4*)(Bptr + (size_t)k0 * N);
        __syncthreads();

#pragma unroll
        for (int k = 0; k < BK; ++k) {
            float a[8], b[8];
            *(float4*)(a)     = *(const float4*)&As[k][ty * 8];
            *(float4*)(a + 4) = *(const float4*)&As[k][ty * 8 + 4];
            *(float4*)(b)     = *(const float4*)&Bs[k][tx * 8];
            *(float4*)(b + 4) = *(const float4*)&Bs[k][tx * 8 + 4];
#pragma unroll
            for (int i = 0; i < 8; ++i)
#pragma unroll
                for (int j = 0; j < 8; ++j)
                    acc[i][j] = fmaf(a[i], b[j], acc[i][j]);
        }
        __syncthreads();
    }

    float bias_r[8];
#pragma unroll
    for (int j = 0; j < 8; ++j) bias_r[j] = bias ? bias[bn + tx * 8 + j] : 0.f;

#pragma unroll
    for (int i = 0; i < 8; ++i) {
        const int row = bm + ty * 8 + i;
        float* cp = C + (size_t)row * N + bn + tx * 8;
        float4 o0, o1;
        float v;
        v = acc[i][0] + bias_r[0]; o0.x = reluOut ? fmaxf(v, 0.f) : v;
        v = acc[i][1] + bias_r[1]; o0.y = reluOut ? fmaxf(v, 0.f) : v;
        v = acc[i][2] + bias_r[2]; o0.z = reluOut ? fmaxf(v, 0.f) : v;
        v = acc[i][3] + bias_r[3]; o0.w = reluOut ? fmaxf(v, 0.f) : v;
        v = acc[i][4] + bias_r[4]; o1.x = reluOut ? fmaxf(v, 0.f) : v;
        v = acc[i][5] + bias_r[5]; o1.y = reluOut ? fmaxf(v, 0.f) : v;
        v = acc[i][6] + bias_r[6]; o1.z = reluOut ? fmaxf(v, 0.f) : v;
        v = acc[i][7] + bias_r[7]; o1.w = reluOut ? fmaxf(v, 0.f) : v;
        *(float4*)cp = o0;
        *(float4*)(cp + 4) = o1;
    }
}

// ================================================================================
// Fused residual + LayerNorm (rows of 256): out = LN(base + delta)*g + b
// ================================================================================
__global__ __launch_bounds__(256)
void ln_kernel(const float* __restrict__ base, const float* __restrict__ delta,
               const float* __restrict__ g, const float* __restrict__ b,
               float* __restrict__ out)
{
    const int row  = blockIdx.x * 8 + (threadIdx.x >> 5);
    const int lane = threadIdx.x & 31;

    const float4* bp = (const float4*)(base  + (size_t)row * DIM);
    const float4* dp = (const float4*)(delta + (size_t)row * DIM);
    float4 x0 = bp[lane],      d0 = dp[lane];
    float4 x1 = bp[32 + lane], d1 = dp[32 + lane];
    float4 u0, u1;
    u0.x = x0.x + d0.x; u0.y = x0.y + d0.y; u0.z = x0.z + d0.z; u0.w = x0.w + d0.w;
    u1.x = x1.x + d1.x; u1.y = x1.y + d1.y; u1.z = x1.z + d1.z; u1.w = x1.w + d1.w;

    float s  = u0.x + u0.y + u0.z + u0.w + u1.x + u1.y + u1.z + u1.w;
    float ss = u0.x*u0.x + u0.y*u0.y + u0.z*u0.z + u0.w*u0.w
             + u1.x*u1.x + u1.y*u1.y + u1.z*u1.z + u1.w*u1.w;
#pragma unroll
    for (int o = 16; o > 0; o >>= 1) {
        s  += __shfl_xor_sync(0xffffffffu, s, o);
        ss += __shfl_xor_sync(0xffffffffu, ss, o);
    }
    const float mean = s * (1.f / DIM);
    const float var  = ss * (1.f / DIM) - mean * mean;
    const float rstd = rsqrtf(var + 1e-6f);

    const float4 gv0 = ((const float4*)g)[lane];
    const float4 gv1 = ((const float4*)g)[32 + lane];
    const float4 bv0 = ((const float4*)b)[lane];
    const float4 bv1 = ((const float4*)b)[32 + lane];

    float4 o0, o1;
    o0.x = (u0.x - mean) * rstd * gv0.x + bv0.x;
    o0.y = (u0.y - mean) * rstd * gv0.y + bv0.y;
    o0.z = (u0.z - mean) * rstd * gv0.z + bv0.z;
    o0.w = (u0.w - mean) * rstd * gv0.w + bv0.w;
    o1.x = (u1.x - mean) * rstd * gv1.x + bv1.x;
    o1.y = (u1.y - mean) * rstd * gv1.y + bv1.y;
    o1.z = (u1.z - mean) * rstd * gv1.z + bv1.z;
    o1.w = (u1.w - mean) * rstd * gv1.w + bv1.w;

    float4* op = (float4*)(out + (size_t)row * DIM);
    op[lane] = o0;
    op[32 + lane] = o1;
}

// ================================================================================
extern "C" void kernel_launch(void* const* d_in, const int* in_sizes, int n_in,
                              void* d_out, int out_size)
{
    (void)in_sizes; (void)n_in; (void)out_size;
    const float* xs  = (const float*)d_in[0];
    const float* h0  = (const float*)d_in[1];
    const float* Wi  = (const float*)d_in[2];
    const float* Wh  = (const float*)d_in[3];
    const float* bh  = (const float*)d_in[4];
    const float* Wg  = (const float*)d_in[5];
    const float* bg  = (const float*)d_in[6];
    const float* g1  = (const float*)d_in[7];
    const float* be1 = (const float*)d_in[8];
    const float* W1  = (const float*)d_in[9];
    const float* b1  = (const float*)d_in[10];
    const float* W2  = (const float*)d_in[11];
    const float* b2  = (const float*)d_in[12];
    const float* g2  = (const float*)d_in[13];
    const float* be2 = (const float*)d_in[14];
    float* out = (float*)d_out;

    float *xg, *ys, *t3, *y, *t1, *t6;
    cudaGetSymbolAddress((void**)&xg, g_xg);
    cudaGetSymbolAddress((void**)&ys, g_ys);
    cudaGetSymbolAddress((void**)&t3, g_t3);
    cudaGetSymbolAddress((void**)&y,  g_y);
    cudaGetSymbolAddress((void**)&t1, g_t1);
    cudaGetSymbolAddress((void**)&t6, g_t6);

    // 1) xg = xs @ Wi
    gemm_kernel<<<dim3(G3 / 128, T_STEPS / 128), 256>>>(xs, Wi, nullptr, xg,
                                                        T_STEPS, G3, DIM, 0, 0);
    // 2) sequential GRU scan -> ys
    scan_kernel<<<NC, SCAN_THREADS>>>(Wh, bh, h0);
    // 3) t3 = relu(ys) @ Wg + bg
    gemm_kernel<<<dim3(DIM / 128, T_STEPS / 128), 256>>>(ys, Wg, bg, t3,
                                                         T_STEPS, DIM, DIM, 1, 0);
    // 4) y = LN(xs + t3) * g1 + be1
    ln_kernel<<<T_STEPS / 8, 256>>>(xs, t3, g1, be1, y);
    // 5) t1 = relu(y @ W1 + b1)
    gemm_kernel<<<dim3(FFN_DIM / 128, T_STEPS / 128), 256>>>(y, W1, b1, t1,
                                                             T_STEPS, FFN_DIM, DIM, 0, 1);
    // 6) t6 = t1 @ W2 + b2
    gemm_kernel<<<dim3(DIM / 128, T_STEPS / 128), 256>>>(t1, W2, b2, t6,
                                                         T_STEPS, DIM, FFN_DIM, 0, 0);
    // 7) out = LN(y + t6) * g2 + be2
    ln_kernel<<<T_STEPS / 8, 256>>>(y, t6, g2, be2, out);
}

// round 7
// speedup vs baseline: 3.3686x; 1.0386x over previous
#include <cuda_runtime.h>
#include <cooperative_groups.h>
#include <math.h>
#include <stdint.h>

namespace cg = cooperative_groups;

#define T_STEPS 32768
#define DIM 256
#define G3 768            // 3*DIM
#define FFN_DIM 1024
#define NC 8              // cluster size (CTAs)
#define SCAN_THREADS 384  // 12 warps, 96 cols x 4 threads/col
#define TX_BYTES 1024     // per-step bytes into each CTA: 8 CTAs * 32 lanes * 4B

// ---------------- scratch (static device allocations; no cudaMalloc allowed) ----
__device__ float g_xg[T_STEPS * G3];
__device__ float g_ys[T_STEPS * DIM];
__device__ float g_t3[T_STEPS * DIM];
__device__ float g_y [T_STEPS * DIM];
__device__ float g_t1[T_STEPS * FFN_DIM];
__device__ float g_t6[T_STEPS * DIM];

// ---------------- packed f32x2 helpers ------------------------------------------
__device__ __forceinline__ unsigned long long pack2(float lo, float hi) {
    unsigned long long r;
    asm("mov.b64 %0, {%1, %2};" : "=l"(r) : "f"(lo), "f"(hi));
    return r;
}
__device__ __forceinline__ unsigned long long dup2(float v) {
    unsigned long long r;
    asm("mov.b64 %0, {%1, %1};" : "=l"(r) : "f"(v));
    return r;
}
__device__ __forceinline__ void fma2(unsigned long long& acc,
                                     unsigned long long a, unsigned long long b) {
    asm("fma.rn.f32x2 %0, %1, %2, %0;" : "+l"(acc) : "l"(a), "l"(b));
}
__device__ __forceinline__ unsigned long long add2(unsigned long long a,
                                                   unsigned long long b) {
    unsigned long long r;
    asm("add.rn.f32x2 %0, %1, %2;" : "=l"(r) : "l"(a), "l"(b));
    return r;
}
__device__ __forceinline__ float hsum2(unsigned long long v) {
    float lo, hi;
    asm("mov.b64 {%0, %1}, %2;" : "=f"(lo), "=f"(hi) : "l"(v));
    return lo + hi;
}

// ---------------- fast transcendentals ------------------------------------------
__device__ __forceinline__ float sigmoid_fast(float x) {
    return __fdividef(1.f, 1.f + __expf(-x));
}
__device__ __forceinline__ float tanh_fast(float x) {
    float e = __expf(2.f * x);
    return 1.f - __fdividef(2.f, e + 1.f);
}

// ---------------- smem / cluster primitives --------------------------------------
__device__ __forceinline__ uint32_t smem_u32(const void* p) {
    uint32_t a;
    asm("{ .reg .u64 t; cvta.to.shared.u64 t, %1; cvt.u32.u64 %0, t; }"
        : "=r"(a) : "l"(p));
    return a;
}
__device__ __forceinline__ uint32_t mapa_u32(uint32_t laddr, uint32_t rank) {
    uint32_t r;
    asm("mapa.shared::cluster.u32 %0, %1, %2;" : "=r"(r) : "r"(laddr), "r"(rank));
    return r;
}
__device__ __forceinline__ void mbar_init(uint32_t mbar, uint32_t count) {
    asm volatile("mbarrier.init.shared.b64 [%0], %1;" :: "r"(mbar), "r"(count) : "memory");
}
__device__ __forceinline__ void mbar_arrive_expect_tx(uint32_t mbar, uint32_t bytes) {
    asm volatile("mbarrier.arrive.expect_tx.shared.b64 _, [%0], %1;"
                 :: "r"(mbar), "r"(bytes) : "memory");
}
__device__ __forceinline__ void mbar_wait_parity_acq(uint32_t mbar, uint32_t parity) {
    asm volatile(
        "{\n\t.reg .pred P;\n\t"
        "WL_%=:\n\t"
        "mbarrier.try_wait.parity.acquire.cluster.shared::cta.b64 P, [%0], %1, 0x989680;\n\t"
        "@P bra.uni WD_%=;\n\t"
        "bra.uni WL_%=;\n\t"
        "WD_%=:\n\t}"
        :: "r"(mbar), "r"(parity) : "memory");
}
// async 4-byte store into a peer CTA's smem; counts toward the peer-local mbarrier
__device__ __forceinline__ void st_async_b32(uint32_t raddr, float v, uint32_t rmbar) {
    asm volatile(
        "st.async.shared::cluster.mbarrier::complete_tx::bytes.b32 [%0], %1, [%2];"
        :: "r"(raddr), "f"(v), "r"(rmbar) : "memory");
}
__device__ __forceinline__ void cluster_arrive_rel() {
    asm volatile("barrier.cluster.arrive.aligned;" ::: "memory");
}
__device__ __forceinline__ void cluster_wait_acq() {
    asm volatile("barrier.cluster.wait.aligned;" ::: "memory");
}

// ================================================================================
// GRU scan: 8-CTA cluster. Wh in registers (f32x2). Step sync = st.async into
// peers' double-buffered h + local transaction-counting mbarrier. No trailing
// block barrier: the tx-barrier transitively orders hg_s reuse (see analysis).
// ================================================================================
__global__ void __cluster_dims__(NC, 1, 1) __launch_bounds__(SCAN_THREADS, 1)
scan_kernel(const float* __restrict__ Wh, const float* __restrict__ bh,
            const float* __restrict__ h0)
{
    cg::cluster_group cluster = cg::this_cluster();
    const unsigned crank = cluster.block_rank();

    __shared__ __align__(16) float h_s[2][DIM];
    __shared__ float hg_s[96];
    __shared__ __align__(8) unsigned long long mbar[2];

    const int tid  = threadIdx.x;
    const int lane = tid & 31;
    const int warp = tid >> 5;
    const int col_local = warp * 8 + (lane & 7);   // 0..95
    const int q  = lane >> 3;                      // k-quarter 0..3
    const int qq = 2 * q;                          // bank-conflict rotation
    const int gate = col_local >> 5;               // 0=r,1=z,2=n
    const int m    = col_local & 31;
    const int gcol = gate * DIM + (int)crank * 32 + m;

    const uint32_t mbar0 = smem_u32(&mbar[0]);
    if (tid == 0) { mbar_init(mbar0, 1); mbar_init(mbar0 + 8, 1); }

    // ---- 64 weights/thread packed into 32 f32x2, rotated chunk order ----
    unsigned long long w2[32];
#pragma unroll
    for (int j = 0; j < 16; ++j) {
        const int cidx = (j + qq) & 15;
        const int k = q * 64 + cidx * 4;
        w2[2 * j + 0] = pack2(Wh[(k + 0) * G3 + gcol], Wh[(k + 1) * G3 + gcol]);
        w2[2 * j + 1] = pack2(Wh[(k + 2) * G3 + gcol], Wh[(k + 3) * G3 + gcol]);
    }
    const float bcol = bh[gcol];

    if (tid < DIM) h_s[0][tid] = h0[tid];

    // gate-warp-only: xg prefetch + remote addresses (each lane stores its 4B)
    float xr = 0.f, xz = 0.f, xn = 0.f;
    uint32_t rdata[NC], rmbar[NC];
    if (tid < 32) {
        const float* p = g_xg + (int)crank * 32 + tid;
        xr = p[0]; xz = p[DIM]; xn = p[2 * DIM];
        const uint32_t ldata = smem_u32(&h_s[0][(int)crank * 32 + lane]);
#pragma unroll
        for (int d = 0; d < NC; ++d) {
            rdata[d] = mapa_u32(ldata, (uint32_t)d);
            rmbar[d] = mapa_u32(mbar0, (uint32_t)d);
        }
    }

    __syncthreads();
    cluster.sync();   // mbarrier inits + h_s[0] visible cluster-wide

#pragma unroll 1
    for (int t = 0; t < T_STEPS; ++t) {
        const int b = t & 1;
        if (t > 0)
            mbar_wait_parity_acq(mbar0 + (uint32_t)(b * 8), (uint32_t)(((t - 1) >> 1) & 1));
        if (tid == 0 && t + 1 < T_STEPS)
            mbar_arrive_expect_tx(mbar0 + (uint32_t)(((t + 1) & 1) * 8), TX_BYTES);

        // ---- matvec: hg[col] = sum_k h[k] * Wh[k, gcol]  (f32x2 packed) ----
        const ulonglong2* hb = (const ulonglong2*)(h_s[b]) + q * 16;
        unsigned long long a0 = 0ull, a1 = 0ull, a2 = 0ull, a3 = 0ull;
#pragma unroll
        for (int j = 0; j < 16; ++j) {
            const int idx = (j + qq) & 15;       // conflict-free LDS rotation
            const ulonglong2 hv = hb[idx];
            fma2((j & 1) ? a2 : a0, w2[2 * j + 0], hv.x);
            fma2((j & 1) ? a3 : a1, w2[2 * j + 1], hv.y);
        }
        float acc = hsum2(add2(add2(a0, a1), add2(a2, a3)));
        acc += __shfl_down_sync(0xffffffffu, acc, 16);
        acc += __shfl_down_sync(0xffffffffu, acc, 8);
        if (q == 0) hg_s[col_local] = acc + bcol;
        __syncthreads();

        // ---- gates + async broadcast (gate warp only) ----
        if (tid < 32) {
            const float hr = hg_s[tid];
            const float hz = hg_s[32 + tid];
            const float hn = hg_s[64 + tid];
            const float r = sigmoid_fast(xr + hr);
            const float z = sigmoid_fast(xz + hz);
            const float nn = tanh_fast(xn + r * hn);
            const float hold = h_s[b][(int)crank * 32 + tid];
            const float hnew = (1.f - z) * nn + z * hold;

            if (t + 1 < T_STEPS) {
                const uint32_t boff = (uint32_t)(((t + 1) & 1) * (DIM * 4));
                const uint32_t moff = (uint32_t)(((t + 1) & 1) * 8);
#pragma unroll
                for (int d = 0; d < NC; ++d)
                    st_async_b32(rdata[d] + boff, hnew, rmbar[d] + moff);
            }

            // off the critical path: record output + prefetch next xg
            g_ys[t * DIM + (int)crank * 32 + tid] = hnew;
            if (t + 1 < T_STEPS) {
                const float* p = g_xg + (t + 1) * G3 + (int)crank * 32 + tid;
                xr = p[0]; xz = p[DIM]; xn = p[2 * DIM];
            }
        }
        // NO trailing __syncthreads: hg_s reuse at t+1 is ordered through the
        // t+1 mbarrier wait, which requires this CTA's gate-warp stores, which
        // follow its hg_s reads. h_s[b] reuse (t+2 remote stores) is ordered the
        // same way through the peers' t+1 waits.
    }

    // keep cluster smem alive until all peers are done (drains in-flight traffic)
    cluster_arrive_rel();
    cluster_wait_acq();
}

// ================================================================================
// fp32 tiled GEMM with packed f32x2 inner loop (correctness proven in round 2).
// BM=BN=128, BK=8, 256 threads, 8x8 micro-tile.
// ================================================================================
__global__ __launch_bounds__(256)
void gemm_kernel(const float* __restrict__ A, const float* __restrict__ B,
                 const float* __restrict__ bias, float* __restrict__ C,
                 int M, int N, int K, int reluA, int reluOut)
{
    constexpr int BM = 128, BN = 128, BK = 8;
    __shared__ __align__(16) float As[BK][BM];
    __shared__ __align__(16) float Bs[BK][BN];

    const int tid = threadIdx.x;
    const int bm = blockIdx.y * BM;
    const int bn = blockIdx.x * BN;
    const int tx = tid & 15;
    const int ty = tid >> 4;

    const int aRow = tid >> 1;
    const int aCol = (tid & 1) * 4;
    const int bRow = tid >> 5;
    const int bCol = (tid & 31) * 4;

    const float* Aptr = A + (size_t)(bm + aRow) * K + aCol;
    const float* Bptr = B + (size_t)bRow * N + bn + bCol;

    unsigned long long acc2[8][4];
#pragma unroll
    for (int i = 0; i < 8; ++i)
#pragma unroll
        for (int j = 0; j < 4; ++j) acc2[i][j] = 0ull;

    for (int k0 = 0; k0 < K; k0 += BK) {
        float4 av = *(const float4*)(Aptr + k0);
        if (reluA) {
            av.x = fmaxf(av.x, 0.f); av.y = fmaxf(av.y, 0.f);
            av.z = fmaxf(av.z, 0.f); av.w = fmaxf(av.w, 0.f);
        }
        As[aCol + 0][aRow] = av.x;
        As[aCol + 1][aRow] = av.y;
        As[aCol + 2][aRow] = av.z;
        As[aCol + 3][aRow] = av.w;
        *(float4*)&Bs[bRow][bCol] = *(const float4*)(Bptr + (size_t)k0 * N);
        __syncthreads();

#pragma unroll
        for (int k = 0; k < BK; ++k) {
            float a[8];
            *(float4*)(a)     = *(const float4*)&As[k][ty * 8];
            *(float4*)(a + 4) = *(const float4*)&As[k][ty * 8 + 4];
            unsigned long long b2[4];
            {
                const ulonglong2 p0 = *(const ulonglong2*)&Bs[k][tx * 8];
                const ulonglong2 p1 = *(const ulonglong2*)&Bs[k][tx * 8 + 4];
                b2[0] = p0.x; b2[1] = p0.y; b2[2] = p1.x; b2[3] = p1.y;
            }
#pragma unroll
            for (int i = 0; i < 8; ++i) {
                const unsigned long long ad = dup2(a[i]);
#pragma unroll
                for (int j = 0; j < 4; ++j) fma2(acc2[i][j], ad, b2[j]);
            }
        }
        __syncthreads();
    }

    float bias_r[8];
#pragma unroll
    for (int j = 0; j < 8; ++j) bias_r[j] = bias ? bias[bn + tx * 8 + j] : 0.f;

#pragma unroll
    for (int i = 0; i < 8; ++i) {
        const int row = bm + ty * 8 + i;
        float* cp = C + (size_t)row * N + bn + tx * 8;
        float o[8];
#pragma unroll
        for (int j = 0; j < 4; ++j) {
            float lo, hi;
            asm("mov.b64 {%0, %1}, %2;" : "=f"(lo), "=f"(hi) : "l"(acc2[i][j]));
            o[2 * j] = lo; o[2 * j + 1] = hi;
        }
#pragma unroll
        for (int j = 0; j < 8; ++j) {
            float v = o[j] + bias_r[j];
            o[j] = reluOut ? fmaxf(v, 0.f) : v;
        }
        *(float4*)cp       = *(float4*)(o);
        *(float4*)(cp + 4) = *(float4*)(o + 4);
    }
}

// ================================================================================
// Fused residual + LayerNorm (rows of 256): out = LN(base + delta)*g + b
// ================================================================================
__global__ __launch_bounds__(256)
void ln_kernel(const float* __restrict__ base, const float* __restrict__ delta,
               const float* __restrict__ g, const float* __restrict__ b,
               float* __restrict__ out)
{
    const int row  = blockIdx.x * 8 + (threadIdx.x >> 5);
    const int lane = threadIdx.x & 31;

    const float4* bp = (const float4*)(base  + (size_t)row * DIM);
    const float4* dp = (const float4*)(delta + (size_t)row * DIM);
    float4 x0 = bp[lane],      d0 = dp[lane];
    float4 x1 = bp[32 + lane], d1 = dp[32 + lane];
    float4 u0, u1;
    u0.x = x0.x + d0.x; u0.y = x0.y + d0.y; u0.z = x0.z + d0.z; u0.w = x0.w + d0.w;
    u1.x = x1.x + d1.x; u1.y = x1.y + d1.y; u1.z = x1.z + d1.z; u1.w = x1.w + d1.w;

    float s  = u0.x + u0.y + u0.z + u0.w + u1.x + u1.y + u1.z + u1.w;
    float ss = u0.x*u0.x + u0.y*u0.y + u0.z*u0.z + u0.w*u0.w
             + u1.x*u1.x + u1.y*u1.y + u1.z*u1.z + u1.w*u1.w;
#pragma unroll
    for (int o = 16; o > 0; o >>= 1) {
        s  += __shfl_xor_sync(0xffffffffu, s, o);
        ss += __shfl_xor_sync(0xffffffffu, ss, o);
    }
    const float mean = s * (1.f / DIM);
    const float var  = ss * (1.f / DIM) - mean * mean;
    const float rstd = rsqrtf(var + 1e-6f);

    const float4 gv0 = ((const float4*)g)[lane];
    const float4 gv1 = ((const float4*)g)[32 + lane];
    const float4 bv0 = ((const float4*)b)[lane];
    const float4 bv1 = ((const float4*)b)[32 + lane];

    float4 o0, o1;
    o0.x = (u0.x - mean) * rstd * gv0.x + bv0.x;
    o0.y = (u0.y - mean) * rstd * gv0.y + bv0.y;
    o0.z = (u0.z - mean) * rstd * gv0.z + bv0.z;
    o0.w = (u0.w - mean) * rstd * gv0.w + bv0.w;
    o1.x = (u1.x - mean) * rstd * gv1.x + bv1.x;
    o1.y = (u1.y - mean) * rstd * gv1.y + bv1.y;
    o1.z = (u1.z - mean) * rstd * gv1.z + bv1.z;
    o1.w = (u1.w - mean) * rstd * gv1.w + bv1.w;

    float4* op = (float4*)(out + (size_t)row * DIM);
    op[lane] = o0;
    op[32 + lane] = o1;
}

// ================================================================================
extern "C" void kernel_launch(void* const* d_in, const int* in_sizes, int n_in,
                              void* d_out, int out_size)
{
    (void)in_sizes; (void)n_in; (void)out_size;
    const float* xs  = (const float*)d_in[0];
    const float* h0  = (const float*)d_in[1];
    const float* Wi  = (const float*)d_in[2];
    const float* Wh  = (const float*)d_in[3];
    const float* bh  = (const float*)d_in[4];
    const float* Wg  = (const float*)d_in[5];
    const float* bg  = (const float*)d_in[6];
    const float* g1  = (const float*)d_in[7];
    const float* be1 = (const float*)d_in[8];
    const float* W1  = (const float*)d_in[9];
    const float* b1  = (const float*)d_in[10];
    const float* W2  = (const float*)d_in[11];
    const float* b2  = (const float*)d_in[12];
    const float* g2  = (const float*)d_in[13];
    const float* be2 = (const float*)d_in[14];
    float* out = (float*)d_out;

    float *xg, *ys, *t3, *y, *t1, *t6;
    cudaGetSymbolAddress((void**)&xg, g_xg);
    cudaGetSymbolAddress((void**)&ys, g_ys);
    cudaGetSymbolAddress((void**)&t3, g_t3);
    cudaGetSymbolAddress((void**)&y,  g_y);
    cudaGetSymbolAddress((void**)&t1, g_t1);
    cudaGetSymbolAddress((void**)&t6, g_t6);

    // 1) xg = xs @ Wi
    gemm_kernel<<<dim3(G3 / 128, T_STEPS / 128), 256>>>(xs, Wi, nullptr, xg,
                                                        T_STEPS, G3, DIM, 0, 0);
    // 2) sequential GRU scan -> ys
    scan_kernel<<<NC, SCAN_THREADS>>>(Wh, bh, h0);
    // 3) t3 = relu(ys) @ Wg + bg
    gemm_kernel<<<dim3(DIM / 128, T_STEPS / 128), 256>>>(ys, Wg, bg, t3,
                                                         T_STEPS, DIM, DIM, 1, 0);
    // 4) y = LN(xs + t3) * g1 + be1
    ln_kernel<<<T_STEPS / 8, 256>>>(xs, t3, g1, be1, y);
    // 5) t1 = relu(y @ W1 + b1)
    gemm_kernel<<<dim3(FFN_DIM / 128, T_STEPS / 128), 256>>>(y, W1, b1, t1,
                                                             T_STEPS, FFN_DIM, DIM, 0, 1);
    // 6) t6 = t1 @ W2 + b2
    gemm_kernel<<<dim3(DIM / 128, T_STEPS / 128), 256>>>(t1, W2, b2, t6,
                                                         T_STEPS, DIM, FFN_DIM, 0, 0);
    // 7) out = LN(y + t6) * g2 + be2
    ln_kernel<<<T_STEPS / 8, 256>>>(y, t6, g2, be2, out);
}